// round 10
// baseline (speedup 1.0000x reference)
#include <cuda_runtime.h>
#include <math.h>

#define HH 224
#define WW 224
#define BB 2
#define PP 2048
#define FF 256
#define SIGMA_F 0.0003f
#define INV_SIGMA 3333.3333333f
#define D2CUT (88.0f * SIGMA_F)      // exp underflow threshold (matches fp32 reference)
#define MARGIN 0.16248077f           // sqrt(D2CUT)

// ---------------------------------------------------------------------------
// Fused kernel: 512 threads/block, 16x8 pixel tile, grid (14, 28, BB).
// Phase 1: threads 0..255 compute per-face data for face = tid (batch b),
//          cull (front & tile-bbox), order-preserving compact into smem.
// Phase 2: 4 threads per pixel, each handles a quarter of the face list.
// Phase 3: merge quarters (ascending order, strict >), write outputs.
// ---------------------------------------------------------------------------
__global__ void __launch_bounds__(512) vcr_fused_kernel(
    const float* __restrict__ pts,
    const int*   __restrict__ faces,
    const float* __restrict__ rot,
    const float* __restrict__ pos,
    const float* __restrict__ proj,
    const float* __restrict__ cols,
    float* __restrict__ out)
{
    __shared__ float4 sf_hot[FF * 3];    // [0]: x2,y2,A0,B0  [1]: A1,B1,z0,z1  [2]: z2,k12,k20,k01
    __shared__ float4 sf_edge[FF * 4];   // [0]: x0,y0,x1,y1  [1..3]: e,i per edge
    __shared__ float4 sf_col[FF * 3];    // colors (9 used of 12)
    __shared__ int    warp_off[8];
    __shared__ int    sm_cnt;
    __shared__ float  cz[3][128], cl0[3][128], cl1[3][128], cl2[3][128], cprod[3][128];
    __shared__ int    cidx[3][128];

    int b   = blockIdx.z;
    int tid = threadIdx.x;

    int tx0 = blockIdx.x * 16;
    int ty0 = blockIdx.y * 8;
    float txmin = (2.0f*tx0 + 1.0f) * (1.0f/WW) - 1.0f;
    float txmax = (2.0f*(tx0+15) + 1.0f) * (1.0f/WW) - 1.0f;
    float tymax = 1.0f - (2.0f*ty0 + 1.0f) * (1.0f/HH);
    float tymin = 1.0f - (2.0f*(ty0+7) + 1.0f) * (1.0f/HH);

    // ---------------- Phase 1a: per-face transform + cull flag ----------------
    bool keep = false;
    unsigned mask = 0;
    int vi0 = 0, vi1 = 0, vi2 = 0;
    float Px[3], Py[3], Pz[3], Qx[3], Qy[3];

    if (tid < FF) {
        int f = tid;
        float R0 = __ldg(&rot[b*9+0]), R1 = __ldg(&rot[b*9+1]), R2 = __ldg(&rot[b*9+2]);
        float R3 = __ldg(&rot[b*9+3]), R4 = __ldg(&rot[b*9+4]), R5 = __ldg(&rot[b*9+5]);
        float R6 = __ldg(&rot[b*9+6]), R7 = __ldg(&rot[b*9+7]), R8 = __ldg(&rot[b*9+8]);
        float cpx = __ldg(&pos[b*3+0]), cpy = __ldg(&pos[b*3+1]), cpz = __ldg(&pos[b*3+2]);
        float pr0 = __ldg(&proj[0]), pr1 = __ldg(&proj[1]), pr2 = __ldg(&proj[2]);

        vi0 = __ldg(&faces[f*3+0]);
        vi1 = __ldg(&faces[f*3+1]);
        vi2 = __ldg(&faces[f*3+2]);
        int vi[3] = { vi0, vi1, vi2 };

        #pragma unroll
        for (int k = 0; k < 3; k++) {
            const float* pp = pts + ((size_t)b * PP + vi[k]) * 3;
            float dx = __ldg(pp+0)-cpx, dy = __ldg(pp+1)-cpy, dz = __ldg(pp+2)-cpz;
            float cx = R0*dx + R1*dy + R2*dz;
            float cy = R3*dx + R4*dy + R5*dz;
            float cz2 = R6*dx + R7*dy + R8*dz;
            Px[k]=cx; Py[k]=cy; Pz[k]=cz2;
            float zz = cz2 * pr2;
            Qx[k] = (cx*pr0)/zz;
            Qy[k] = (cy*pr1)/zz;
        }

        float ux=Px[1]-Px[0], uy=Py[1]-Py[0], uz=Pz[1]-Pz[0];
        float vx=Px[2]-Px[0], vy=Py[2]-Py[0], vz=Pz[2]-Pz[0];
        float nx = uy*vz - uz*vy;
        float ny = uz*vx - ux*vz;
        float nz = ux*vy - uy*vx;

        // normal1 output written once per batch (block 0,0)
        if (blockIdx.x == 0 && blockIdx.y == 0) {
            float inv = 1.0f / sqrtf(nx*nx + ny*ny + nz*nz + 1e-10f);
            size_t noff = (size_t)BB*HH*WW*3 + (size_t)BB*HH*WW + ((size_t)b*FF + f)*3;
            out[noff+0] = nx*inv;
            out[noff+1] = ny*inv;
            out[noff+2] = nz*inv;
        }

        bool front = (nz > 0.0f);
        float bxmin = fminf(Qx[0], fminf(Qx[1], Qx[2]));
        float bxmax = fmaxf(Qx[0], fmaxf(Qx[1], Qx[2]));
        float bymin = fminf(Qy[0], fminf(Qy[1], Qy[2]));
        float bymax = fmaxf(Qy[0], fmaxf(Qy[1], Qy[2]));
        keep = front &
               (bxmin - MARGIN <= txmax) & (bxmax + MARGIN >= txmin) &
               (bymin - MARGIN <= tymax) & (bymax + MARGIN >= tymin);

        mask = __ballot_sync(0xffffffffu, keep);
        if ((tid & 31) == 0) warp_off[tid >> 5] = __popc(mask);
    }
    __syncthreads();
    if (tid == 0) {
        int s = 0;
        #pragma unroll
        for (int i = 0; i < 8; i++) { int t = warp_off[i]; warp_off[i] = s; s += t; }
        sm_cnt = s;
    }
    __syncthreads();

    // ---------------- Phase 1b: derive + write compacted smem ----------------
    if (tid < FF && keep) {
        int lane = tid & 31;
        int slot = warp_off[tid >> 5] + __popc(mask & ((1u << lane) - 1u));

        float denom = (Qy[1]-Qy[2])*(Qx[0]-Qx[2]) + (Qx[2]-Qx[1])*(Qy[0]-Qy[2]);
        if (fabsf(denom) < 1e-10f) denom = 1e-10f;
        float invden = 1.0f / denom;
        float den2 = denom * denom;

        float e01x = Qx[1]-Qx[0], e01y = Qy[1]-Qy[0];
        float e12x = Qx[2]-Qx[1], e12y = Qy[2]-Qy[1];
        float e20x = Qx[0]-Qx[2], e20y = Qy[0]-Qy[2];
        float i01 = 1.0f/(e01x*e01x + e01y*e01y + 1e-10f);
        float i12 = 1.0f/(e12x*e12x + e12y*e12y + 1e-10f);
        float i20 = 1.0f/(e20x*e20x + e20y*e20y + 1e-10f);

        sf_hot[slot*3+0] = make_float4(Qx[2], Qy[2], (Qy[1]-Qy[2])*invden, (Qx[2]-Qx[1])*invden);
        sf_hot[slot*3+1] = make_float4((Qy[2]-Qy[0])*invden, (Qx[0]-Qx[2])*invden, Pz[0], Pz[1]);
        sf_hot[slot*3+2] = make_float4(Pz[2], den2*i12, den2*i20, den2*i01);
        sf_edge[slot*4+0] = make_float4(Qx[0], Qy[0], Qx[1], Qy[1]);
        sf_edge[slot*4+1] = make_float4(e01x, e01y, i01, 0.0f);
        sf_edge[slot*4+2] = make_float4(e12x, e12y, i12, 0.0f);
        sf_edge[slot*4+3] = make_float4(e20x, e20y, i20, 0.0f);

        const float* c0p = cols + ((size_t)b * PP + vi0) * 3;
        const float* c1p = cols + ((size_t)b * PP + vi1) * 3;
        const float* c2p = cols + ((size_t)b * PP + vi2) * 3;
        sf_col[slot*3+0] = make_float4(__ldg(c0p+0), __ldg(c0p+1), __ldg(c0p+2), __ldg(c1p+0));
        sf_col[slot*3+1] = make_float4(__ldg(c1p+1), __ldg(c1p+2), __ldg(c2p+0), __ldg(c2p+1));
        sf_col[slot*3+2] = make_float4(__ldg(c2p+2), 0.0f, 0.0f, 0.0f);
    }
    __syncthreads();
    int m = sm_cnt;

    // ---------------- Phase 2: render, 4 threads per pixel ----------------
    int quarter = tid >> 7;           // 0..3
    int q       = tid & 127;
    int x = tx0 + (q & 15);
    int y = ty0 + (q >> 4);
    float px = (2.0f*x + 1.0f) * (1.0f/WW) - 1.0f;
    float py = 1.0f - (2.0f*y + 1.0f) * (1.0f/HH);

    const float IN_F = 1.0f - (1.0f - 1e-7f);   // exact (Sterbenz)

    int ibeg = (m * quarter) >> 2;
    int iend = (m * (quarter + 1)) >> 2;

    float best = -1e10f;
    int   bi   = -1;
    float bl0 = 0.0f, bl1 = 0.0f, bl2 = 0.0f;
    float prod = 1.0f;

    #pragma unroll 2
    for (int i = ibeg; i < iend; i++) {
        float4 v0 = sf_hot[i*3+0];
        float4 v1 = sf_hot[i*3+1];
        float4 v2 = sf_hot[i*3+2];

        float dx = px - v0.x, dy = py - v0.y;
        float l0 = fmaf(v0.z, dx, v0.w * dy);
        float l1 = fmaf(v1.x, dx, v1.y * dy);
        float l2 = 1.0f - l0 - l1;

        if (fminf(l0, fminf(l1, l2)) >= 0.0f) {
            float z = l0*v1.z + l1*v1.w + l2*v2.x;
            if (z > best) { best = z; bi = i; bl0 = l0; bl1 = l1; bl2 = l2; }
            prod *= IN_F;
        } else {
            float lb2 = 0.0f;
            if (l0 < 0.0f) lb2 = l0*l0*v2.y;
            if (l1 < 0.0f) lb2 = fmaxf(lb2, l1*l1*v2.z);
            if (l2 < 0.0f) lb2 = fmaxf(lb2, l2*l2*v2.w);
            if (lb2 < D2CUT) {
                float4 v3 = sf_edge[i*4+0];
                float4 v4 = sf_edge[i*4+1];
                float4 v5 = sf_edge[i*4+2];
                float4 v6 = sf_edge[i*4+3];

                float pax = px - v3.x, pay = py - v3.y;     // from v0
                float t = fminf(fmaxf((pax*v4.x + pay*v4.y)*v4.z, 0.0f), 1.0f);
                float ddx = pax - t*v4.x, ddy = pay - t*v4.y;
                float d2 = ddx*ddx + ddy*ddy;

                pax = px - v3.z; pay = py - v3.w;           // from v1
                t = fminf(fmaxf((pax*v5.x + pay*v5.y)*v5.z, 0.0f), 1.0f);
                ddx = pax - t*v5.x; ddy = pay - t*v5.y;
                d2 = fminf(d2, ddx*ddx + ddy*ddy);

                pax = px - v0.x; pay = py - v0.y;           // from v2
                t = fminf(fmaxf((pax*v6.x + pay*v6.y)*v6.z, 0.0f), 1.0f);
                ddx = pax - t*v6.x; ddy = pay - t*v6.y;
                d2 = fminf(d2, ddx*ddx + ddy*ddy);

                if (d2 < D2CUT) {
                    float p = __expf(-d2 * INV_SIGMA) * (1.0f - 1e-7f);
                    prod *= fmaxf(1.0f - p, 0.0f);
                }
            }
        }
    }

    // ---------------- Phase 3: merge quarters ----------------
    if (quarter > 0) {
        int k = quarter - 1;
        cz[k][q] = best; cidx[k][q] = bi;
        cl0[k][q] = bl0; cl1[k][q] = bl1; cl2[k][q] = bl2;
        cprod[k][q] = prod;
    }
    __syncthreads();
    if (quarter == 0) {
        #pragma unroll
        for (int k = 0; k < 3; k++) {
            float zk = cz[k][q];
            if (zk > best) {          // strict: ties go to lowest quarter/index
                best = zk; bi = cidx[k][q];
                bl0 = cl0[k][q]; bl1 = cl1[k][q]; bl2 = cl2[k][q];
            }
            prod *= cprod[k][q];
        }

        float r = 0.0f, g = 0.0f, bcol = 0.0f;
        if (bi >= 0) {
            float4 c0 = sf_col[bi*3+0];
            float4 c1 = sf_col[bi*3+1];
            float4 c2 = sf_col[bi*3+2];
            r    = bl0*c0.x + bl1*c0.w + bl2*c1.z;
            g    = bl0*c0.y + bl1*c1.x + bl2*c1.w;
            bcol = bl0*c0.z + bl1*c1.y + bl2*c2.x;
        }

        size_t ro = ((size_t)(b*HH + y)*WW + x)*3;
        out[ro+0] = r;
        out[ro+1] = g;
        out[ro+2] = bcol;
        size_t po = (size_t)BB*HH*WW*3 + (size_t)(b*HH + y)*WW + x;
        out[po] = 1.0f - prod;
    }
}

extern "C" void kernel_launch(void* const* d_in, const int* in_sizes, int n_in,
                              void* d_out, int out_size)
{
    const float* pts   = (const float*)d_in[0];
    const int*   faces = (const int*)d_in[1];
    const float* rot   = (const float*)d_in[2];
    const float* pos   = (const float*)d_in[3];
    const float* proj  = (const float*)d_in[4];
    const float* cols  = (const float*)d_in[5];
    float* out = (float*)d_out;

    dim3 grid(WW/16, HH/8, BB);   // 14 x 28 x 2 = 784 blocks x 512 threads
    vcr_fused_kernel<<<grid, 512>>>(pts, faces, rot, pos, proj, cols, out);
}